// round 16
// baseline (speedup 1.0000x reference)
#include <cuda_runtime.h>
#include <cuda_fp16.h>
#include <cuda_bf16.h>
#include <math.h>
#include <stdint.h>

#define BB 8
#define NN 4096
#define MM 4096
#define DD 128

#define BK 64                // bf16 k-chunk per stage (4 x k16 mma steps)
#define NSTEPS 16            // BB * (DD/BK)

// ---- device scratch (static; no allocations) ----
__device__ unsigned int g_fwd[BB * MM];
__device__ float g_x2[BB * NN];
__device__ float g_y2[BB * MM];
__device__ float g_bwd_part[2048];
__device__ float g_fwd_part[128];

__device__ __nv_bfloat16 g_xc[BB * NN * DD];   // bf16 copies
__device__ __nv_bfloat16 g_yc[BB * MM * DD];

// ---- helpers ----
__device__ __forceinline__ uint32_t pack_bf16(float lo, float hi) {
    uint32_t r;
    asm("cvt.rn.bf16x2.f32 %0, %1, %2;" : "=r"(r) : "f"(hi), "f"(lo));
    return r;
}
__device__ __forceinline__ uint32_t smem_u32(const void* p) {
    uint32_t a;
    asm("{ .reg .u64 t; cvta.to.shared.u64 t, %1; cvt.u32.u64 %0, t; }" : "=r"(a) : "l"(p));
    return a;
}
__device__ __forceinline__ void cp_async16(uint32_t dst, const void* src) {
    asm volatile("cp.async.cg.shared.global [%0], [%1], 16;" :: "r"(dst), "l"(src) : "memory");
}
__device__ __forceinline__ void ldsm4(uint32_t a[4], uint32_t addr) {
    asm volatile("ldmatrix.sync.aligned.m8n8.x4.shared.b16 {%0,%1,%2,%3}, [%4];"
                 : "=r"(a[0]), "=r"(a[1]), "=r"(a[2]), "=r"(a[3]) : "r"(addr));
}
__device__ __forceinline__ void mma_bf16(float c[4], const uint32_t a[4], const uint32_t b[2]) {
    asm volatile(
        "mma.sync.aligned.m16n8k16.row.col.f32.bf16.bf16.f32 "
        "{%0,%1,%2,%3}, {%4,%5,%6,%7}, {%8,%9}, {%0,%1,%2,%3};"
        : "+f"(c[0]), "+f"(c[1]), "+f"(c[2]), "+f"(c[3])
        : "r"(a[0]), "r"(a[1]), "r"(a[2]), "r"(a[3]), "r"(b[0]), "r"(b[1]));
}

// ---------------------------------------------------------------------------
// Fused prepass: one read of X,Y -> bf16 copies + row norms + g_fwd init.
__global__ void prepass_kernel(const float* __restrict__ X, const float* __restrict__ Y) {
    const int gw   = (blockIdx.x * blockDim.x + threadIdx.x) >> 5;
    const int lane = threadIdx.x & 31;
    const int half = lane >> 4;
    const int l16  = lane & 15;
    int r = gw * 2 + half;

    const float* src;
    __nv_bfloat16* dstc;
    float* dstn;
    bool isY = false;
    if (r < BB * NN) {
        src = X; dstc = g_xc; dstn = g_x2;
    } else {
        r -= BB * NN;
        if (r >= BB * MM) return;
        src = Y; dstc = g_yc; dstn = g_y2; isY = true;
    }

    const float4* p = (const float4*)(src + (size_t)r * DD) + l16 * 2;
    float4 v0 = p[0], v1 = p[1];
    uint4 o;
    o.x = pack_bf16(v0.x, v0.y);
    o.y = pack_bf16(v0.z, v0.w);
    o.z = pack_bf16(v1.x, v1.y);
    o.w = pack_bf16(v1.z, v1.w);
    *(uint4*)(dstc + (size_t)r * DD + l16 * 8) = o;

    float s = v0.x * v0.x + v0.y * v0.y + v0.z * v0.z + v0.w * v0.w
            + v1.x * v1.x + v1.y * v1.y + v1.z * v1.z + v1.w * v1.w;
    #pragma unroll
    for (int off = 1; off < 16; off <<= 1)
        s += __shfl_xor_sync(0xffffffffu, s, off);
    if (l16 == 0) {
        dstn[r] = s;
        if (isY) g_fwd[r] = 0x7F800000u;   // +inf
    }
}

// ---------------------------------------------------------------------------
// Main: CTA = 64n x 128m, 4 warps (2x2), each warp 32n x 64m, 3 CTAs/SM,
// mma.sync m16n8k16 bf16 + ldmatrix.x4, BK=64 stages, XOR-swizzled smem
// (no padding), 3-buffer pipeline (prefetch distance 2), fully unrolled.
__global__ __launch_bounds__(128, 3) void chamfer_mma() {
    // 16B-chunk XOR swizzle: phys_chunk = chunk ^ (row & 7); row stride 128B.
    __shared__ uint32_t sA0[64 * 32],  sA1[64 * 32],  sA2[64 * 32];
    __shared__ uint32_t sB0[128 * 32], sB1[128 * 32], sB2[128 * 32];
    __shared__ float red[4];

    const int tid   = threadIdx.x;
    const int wid   = tid >> 5;
    const int lane  = tid & 31;
    const int g     = lane >> 2;     // row group 0..7
    const int tig   = lane & 3;      // thread in group
    const int mWarp = wid >> 1;      // 0..1 -> rows mWarp*32
    const int nWarp = wid & 1;       // 0..1 -> cols nWarp*64
    const int nTile = blockIdx.y * 64;
    const int mTile = blockIdx.x * 128;

    const uint32_t aBufs[3] = { smem_u32(sA0), smem_u32(sA1), smem_u32(sA2) };
    const uint32_t bBufs[3] = { smem_u32(sB0), smem_u32(sB1), smem_u32(sB2) };

    // ldsm per-lane components
    const uint32_t x7 = (uint32_t)(lane & 7);          // row&7 for both A and B rows
    // A: row = mWarp*32 + mt*16 + (lane&15); chunk base = lane>>4
    const uint32_t arow = (uint32_t)(mWarp * 32 + (lane & 15)) * 128;
    const uint32_t ca   = (uint32_t)(lane >> 4);
    // B: row = nWarp*64 + ntp*16 + ((lane>>4)<<3) + (lane&7); chunk base = (lane>>3)&1
    const uint32_t brow = (uint32_t)(nWarp * 64 + ((lane >> 4) << 3) + (lane & 7)) * 128;
    const uint32_t cb   = (uint32_t)((lane >> 3) & 1);

    // cp.async: row crow (0..15, +16 per iter), chunk cch; phys chunk fixed per thread
    const int crow = tid >> 3;       // 0..15
    const int cch  = tid & 7;        // chunk 0..7
    const uint32_t cwoff = (uint32_t)(crow * 128 + ((cch ^ (crow & 7)) << 4));
    const uint32_t rowStride16 = 16u * 128u;   // bytes
    const __nv_bfloat16* pxa0 = g_xc + (size_t)(nTile + crow) * DD + cch * 8;
    const __nv_bfloat16* pyb0 = g_yc + (size_t)(mTile + crow) * DD + cch * 8;

    float c[2][8][4];
    #pragma unroll
    for (int mt = 0; mt < 2; mt++)
        #pragma unroll
        for (int nt = 0; nt < 8; nt++)
            #pragma unroll
            for (int k = 0; k < 4; k++) c[mt][nt][k] = 0.f;

    half2 bwd2[2][8][2];
    const half2 hinf = __floats2half2_rn(65504.f, 65504.f);
    #pragma unroll
    for (int mt = 0; mt < 2; mt++)
        #pragma unroll
        for (int nt = 0; nt < 8; nt++) {
            bwd2[mt][nt][0] = hinf;
            bwd2[mt][nt][1] = hinf;
        }

    // ---- stage loader (A 8KB + B 16KB per stage) ----
    auto issue_stage = [&](uint32_t aB, uint32_t bB, const __nv_bfloat16* px,
                           const __nv_bfloat16* py) {
        #pragma unroll
        for (int it = 0; it < 4; ++it)
            cp_async16(aB + cwoff + it * rowStride16, px + (size_t)(it * 16) * DD);
        #pragma unroll
        for (int it = 0; it < 8; ++it)
            cp_async16(bB + cwoff + it * rowStride16, py + (size_t)(it * 16) * DD);
        asm volatile("cp.async.commit_group;" ::: "memory");
    };

    // preload stages 0 and 1
    issue_stage(aBufs[0], bBufs[0], pxa0, pyb0);
    issue_stage(aBufs[1], bBufs[1], pxa0 + BK, pyb0 + BK);

    #pragma unroll
    for (int s = 0; s < NSTEPS; ++s) {
        const int b   = s >> 1;
        const int ch  = s & 1;
        const int buf = s % 3;                   // compile-time (unrolled)
        const uint32_t aBase = aBufs[buf];
        const uint32_t bBase = bBufs[buf];

        // stage s landed (stage s+1 may still be in flight)
        asm volatile("cp.async.wait_group 1;" ::: "memory");
        __syncthreads();

        // kk=0 fragments first (latency overlaps the cp.async burst below)
        uint32_t af[2][2][4], bf[2][4][4];
        ldsm4(af[0][0], aBase + arow + ((ca ^ x7) << 4));
        ldsm4(af[0][1], aBase + arow + 16u * 128u + ((ca ^ x7) << 4));
        ldsm4(bf[0][0], bBase + brow + ((cb ^ x7) << 4));
        ldsm4(bf[0][1], bBase + brow + 16u * 128u + ((cb ^ x7) << 4));
        ldsm4(bf[0][2], bBase + brow + 32u * 128u + ((cb ^ x7) << 4));
        ldsm4(bf[0][3], bBase + brow + 48u * 128u + ((cb ^ x7) << 4));

        // issue stage s+2 into buffer (s+2)%3 (stage s-1's buffer, freed by sync)
        if (s + 2 < NSTEPS) {
            const size_t o2 = (size_t)((s + 2) >> 1) * NN * DD + (size_t)(((s + 2) & 1) * BK);
            issue_stage(aBufs[(s + 2) % 3], bBufs[(s + 2) % 3], pxa0 + o2, pyb0 + o2);
        } else {
            asm volatile("cp.async.commit_group;" ::: "memory");
        }

        // ---- compute: 4 k16 sub-steps, fragment double-buffered ----
        #pragma unroll
        for (int kk = 0; kk < 4; ++kk) {
            const int pb = kk & 1;
            if (kk < 3) {
                const uint32_t cA = (uint32_t)(ca + 2 * (kk + 1));
                const uint32_t cB = (uint32_t)(cb + 2 * (kk + 1));
                ldsm4(af[pb ^ 1][0], aBase + arow + ((cA ^ x7) << 4));
                ldsm4(af[pb ^ 1][1], aBase + arow + 16u * 128u + ((cA ^ x7) << 4));
                ldsm4(bf[pb ^ 1][0], bBase + brow + ((cB ^ x7) << 4));
                ldsm4(bf[pb ^ 1][1], bBase + brow + 16u * 128u + ((cB ^ x7) << 4));
                ldsm4(bf[pb ^ 1][2], bBase + brow + 32u * 128u + ((cB ^ x7) << 4));
                ldsm4(bf[pb ^ 1][3], bBase + brow + 48u * 128u + ((cB ^ x7) << 4));
            }
            #pragma unroll
            for (int mt = 0; mt < 2; ++mt)
                #pragma unroll
                for (int ntp = 0; ntp < 4; ++ntp) {
                    mma_bf16(c[mt][2 * ntp],     af[pb][mt], &bf[pb][ntp][0]);
                    mma_bf16(c[mt][2 * ntp + 1], af[pb][mt], &bf[pb][ntp][2]);
                }
        }

        if (ch == 1) {
            // ---- epilogue for batch b ----
            float x2v[2][2], y2v[8][2];
            #pragma unroll
            for (int mt = 0; mt < 2; mt++) {
                int r = b * NN + nTile + mWarp * 32 + mt * 16 + g;
                x2v[mt][0] = g_x2[r];
                x2v[mt][1] = g_x2[r + 8];
            }
            #pragma unroll
            for (int nt = 0; nt < 8; nt++) {
                int col = b * MM + mTile + nWarp * 64 + nt * 8 + 2 * tig;
                y2v[nt][0] = g_y2[col];
                y2v[nt][1] = g_y2[col + 1];
            }

            #pragma unroll
            for (int nt = 0; nt < 8; nt++) {
                float cm0 = INFINITY, cm1 = INFINITY;
                #pragma unroll
                for (int mt = 0; mt < 2; mt++) {
                    #pragma unroll
                    for (int h = 0; h < 2; h++) {
                        float xy0 = c[mt][nt][2 * h + 0];
                        float xy1 = c[mt][nt][2 * h + 1];
                        float d20 = fmaxf(fmaf(-2.f, xy0, x2v[mt][h] + y2v[nt][0]), 0.f);
                        float d21 = fmaxf(fmaf(-2.f, xy1, x2v[mt][h] + y2v[nt][1]), 0.f);
                        bwd2[mt][nt][h] =
                            __hmin2(bwd2[mt][nt][h], __floats2half2_rn(d20, d21));
                        cm0 = fminf(cm0, d20);
                        cm1 = fminf(cm1, d21);
                        c[mt][nt][2 * h + 0] = 0.f;
                        c[mt][nt][2 * h + 1] = 0.f;
                    }
                }
                // reduce over the 8 row-groups (lanes differing in g)
                #pragma unroll
                for (int o = 4; o <= 16; o <<= 1) {
                    cm0 = fminf(cm0, __shfl_xor_sync(0xffffffffu, cm0, o));
                    cm1 = fminf(cm1, __shfl_xor_sync(0xffffffffu, cm1, o));
                }
                if (g == 0) {
                    int col = b * MM + mTile + nWarp * 64 + nt * 8 + 2 * tig;
                    atomicMin(&g_fwd[col],     __float_as_uint(cm0));
                    atomicMin(&g_fwd[col + 1], __float_as_uint(cm1));
                }
            }
        }
    }

    // ---- backward: min over b complete -> sqrt + block sum ----
    float bsum = 0.f;
    #pragma unroll
    for (int mt = 0; mt < 2; mt++)
        #pragma unroll
        for (int nt = 0; nt < 8; nt++)
            #pragma unroll
            for (int h = 0; h < 2; h++) {
                float2 f = __half22float2(bwd2[mt][nt][h]);
                bsum += sqrtf(f.x) + sqrtf(f.y);
            }
    #pragma unroll
    for (int o = 16; o; o >>= 1) bsum += __shfl_xor_sync(0xffffffffu, bsum, o);
    if (lane == 0) red[wid] = bsum;
    __syncthreads();
    if (tid < 4) {
        float v = red[tid];
        #pragma unroll
        for (int o = 2; o; o >>= 1) v += __shfl_xor_sync(0xfu, v, o);
        if (tid == 0) g_bwd_part[blockIdx.y * gridDim.x + blockIdx.x] = v;
    }
}

// ---------------------------------------------------------------------------
// 128 blocks x 256 threads, 1 element per thread.
__global__ void fwd_reduce_kernel() {
    __shared__ float red[8];
    int tid = threadIdx.x;
    float s = sqrtf(__uint_as_float(g_fwd[blockIdx.x * 256 + tid]));
    #pragma unroll
    for (int o = 16; o; o >>= 1) s += __shfl_xor_sync(0xffffffffu, s, o);
    if ((tid & 31) == 0) red[tid >> 5] = s;
    __syncthreads();
    if (tid < 8) {
        float v = red[tid];
        #pragma unroll
        for (int o = 4; o; o >>= 1) v += __shfl_xor_sync(0xffu, v, o);
        if (tid == 0) g_fwd_part[blockIdx.x] = v;
    }
}

__global__ void final_kernel(float* __restrict__ out) {
    __shared__ float red[256];
    int tid = threadIdx.x;

    float s1 = (tid < 128) ? g_fwd_part[tid] : 0.f;
    float s2 = 0.f;
    #pragma unroll
    for (int r = 0; r < 8; r++)
        s2 += g_bwd_part[r * 256 + tid];

    red[tid] = s1;
    __syncthreads();
    for (int o = 128; o; o >>= 1) {
        if (tid < o) red[tid] += red[tid + o];
        __syncthreads();
    }
    float fwd_sum = red[0];
    __syncthreads();

    red[tid] = s2;
    __syncthreads();
    for (int o = 128; o; o >>= 1) {
        if (tid < o) red[tid] += red[tid + o];
        __syncthreads();
    }

    if (tid == 0)
        out[0] = fwd_sum / (float)(BB * MM) + red[0] / ((float)NN * (float)MM);
}

// ---------------------------------------------------------------------------
extern "C" void kernel_launch(void* const* d_in, const int* in_sizes, int n_in,
                              void* d_out, int out_size) {
    const float* X = (const float*)d_in[0];   // predicted_set (B,N,D)
    const float* Y = (const float*)d_in[1];   // target_set    (B,M,D)

    prepass_kernel<<<(BB * NN + BB * MM) / 16, 256>>>(X, Y);
    dim3 grid(MM / 128, NN / 64);
    chamfer_mma<<<grid, 128>>>();
    fwd_reduce_kernel<<<128, 256>>>();
    final_kernel<<<1, 256>>>((float*)d_out);
}

// round 17
// speedup vs baseline: 1.0248x; 1.0248x over previous
#include <cuda_runtime.h>
#include <cuda_fp16.h>
#include <cuda_bf16.h>
#include <math.h>
#include <stdint.h>

#define BB 8
#define NN 4096
#define MM 4096
#define DD 128

#define BK 64                // bf16 k-chunk per stage (4 x k16 mma steps)
#define ST 36                // smem row stride in 32-bit words (32 data + 4 pad)
#define NSTEPS 16            // BB * (DD/BK)

// ---- device scratch (static; no allocations) ----
__device__ unsigned int g_fwd[BB * MM];
__device__ float g_x2[BB * NN];
__device__ float g_y2[BB * MM];
__device__ float g_bwd_part[2048];
__device__ float g_fwd_part[128];

__device__ __nv_bfloat16 g_xc[BB * NN * DD];   // bf16 copies
__device__ __nv_bfloat16 g_yc[BB * MM * DD];

// ---- helpers ----
__device__ __forceinline__ uint32_t pack_bf16(float lo, float hi) {
    uint32_t r;
    asm("cvt.rn.bf16x2.f32 %0, %1, %2;" : "=r"(r) : "f"(hi), "f"(lo));
    return r;
}
__device__ __forceinline__ uint32_t smem_u32(const void* p) {
    uint32_t a;
    asm("{ .reg .u64 t; cvta.to.shared.u64 t, %1; cvt.u32.u64 %0, t; }" : "=r"(a) : "l"(p));
    return a;
}
__device__ __forceinline__ void cp_async16(uint32_t dst, const void* src) {
    asm volatile("cp.async.cg.shared.global [%0], [%1], 16;" :: "r"(dst), "l"(src) : "memory");
}
__device__ __forceinline__ void ldsm4(uint32_t a[4], uint32_t addr) {
    asm volatile("ldmatrix.sync.aligned.m8n8.x4.shared.b16 {%0,%1,%2,%3}, [%4];"
                 : "=r"(a[0]), "=r"(a[1]), "=r"(a[2]), "=r"(a[3]) : "r"(addr));
}
__device__ __forceinline__ void mma_bf16(float c[4], const uint32_t a[4], const uint32_t b[2]) {
    asm volatile(
        "mma.sync.aligned.m16n8k16.row.col.f32.bf16.bf16.f32 "
        "{%0,%1,%2,%3}, {%4,%5,%6,%7}, {%8,%9}, {%0,%1,%2,%3};"
        : "+f"(c[0]), "+f"(c[1]), "+f"(c[2]), "+f"(c[3])
        : "r"(a[0]), "r"(a[1]), "r"(a[2]), "r"(a[3]), "r"(b[0]), "r"(b[1]));
}

// ---------------------------------------------------------------------------
// Fused prepass: one read of X,Y -> bf16 copies + row norms + g_fwd init.
__global__ void prepass_kernel(const float* __restrict__ X, const float* __restrict__ Y) {
    const int gw   = (blockIdx.x * blockDim.x + threadIdx.x) >> 5;
    const int lane = threadIdx.x & 31;
    const int half = lane >> 4;
    const int l16  = lane & 15;
    int r = gw * 2 + half;

    const float* src;
    __nv_bfloat16* dstc;
    float* dstn;
    bool isY = false;
    if (r < BB * NN) {
        src = X; dstc = g_xc; dstn = g_x2;
    } else {
        r -= BB * NN;
        if (r >= BB * MM) return;
        src = Y; dstc = g_yc; dstn = g_y2; isY = true;
    }

    const float4* p = (const float4*)(src + (size_t)r * DD) + l16 * 2;
    float4 v0 = p[0], v1 = p[1];
    uint4 o;
    o.x = pack_bf16(v0.x, v0.y);
    o.y = pack_bf16(v0.z, v0.w);
    o.z = pack_bf16(v1.x, v1.y);
    o.w = pack_bf16(v1.z, v1.w);
    *(uint4*)(dstc + (size_t)r * DD + l16 * 8) = o;

    float s = v0.x * v0.x + v0.y * v0.y + v0.z * v0.z + v0.w * v0.w
            + v1.x * v1.x + v1.y * v1.y + v1.z * v1.z + v1.w * v1.w;
    #pragma unroll
    for (int off = 1; off < 16; off <<= 1)
        s += __shfl_xor_sync(0xffffffffu, s, off);
    if (l16 == 0) {
        dstn[r] = s;
        if (isY) g_fwd[r] = 0x7F800000u;   // +inf
    }
}

// ---------------------------------------------------------------------------
// Main: CTA = 64n x 128m, 4 warps (2x2), each warp 32n x 64m, 3 CTAs/SM,
// mma.sync m16n8k16 bf16 + ldmatrix.x4, BK=64 double-buffered stages,
// intra-stage fragment double-buffering, row norms cached in smem.
__global__ __launch_bounds__(128, 3) void chamfer_mma() {
    __shared__ uint32_t sA0[64 * ST],  sA1[64 * ST];
    __shared__ uint32_t sB0[128 * ST], sB1[128 * ST];
    __shared__ float s_x2[BB * 64];    // x norms for this CTA's 64 rows, all batches
    __shared__ float s_y2[BB * 128];   // y norms for this CTA's 128 cols, all batches
    __shared__ float red[4];

    const int tid   = threadIdx.x;
    const int wid   = tid >> 5;
    const int lane  = tid & 31;
    const int g     = lane >> 2;     // row group 0..7
    const int tig   = lane & 3;      // thread in group
    const int mWarp = wid >> 1;      // 0..1 -> rows mWarp*32
    const int nWarp = wid & 1;       // 0..1 -> cols nWarp*64
    const int nTile = blockIdx.y * 64;
    const int mTile = blockIdx.x * 128;

    const uint32_t aBufs[2] = { smem_u32(sA0), smem_u32(sA1) };
    const uint32_t bBufs[2] = { smem_u32(sB0), smem_u32(sB1) };

    // ldmatrix per-lane byte offsets (kk adds kk*32 bytes)
    const uint32_t aOff = (uint32_t)((mWarp * 32 + (lane & 15)) * ST + 4 * (lane >> 4)) * 4;
    const uint32_t bOff = (uint32_t)((nWarp * 64 + ((lane >> 4) << 3) + (lane & 7)) * ST
                                     + 4 * ((lane >> 3) & 1)) * 4;

    // cp.async: 8 chunks/row of 16B; A 4 iters (16 rows each), B 8 iters
    const int crow = tid >> 3;       // 0..15
    const int cch  = tid & 7;        // chunk 0..7
    const __nv_bfloat16* pxa = g_xc + (size_t)(nTile + crow) * DD + cch * 8;
    const __nv_bfloat16* pyb = g_yc + (size_t)(mTile + crow) * DD + cch * 8;
    const uint32_t cwoff = (uint32_t)(crow * ST + 4 * cch) * 4;
    const uint32_t rowStride16 = (uint32_t)(16 * ST) * 4;   // 16 rows in bytes

    float c[2][8][4];
    #pragma unroll
    for (int mt = 0; mt < 2; mt++)
        #pragma unroll
        for (int nt = 0; nt < 8; nt++)
            #pragma unroll
            for (int k = 0; k < 4; k++) c[mt][nt][k] = 0.f;

    half2 bwd2[2][8][2];
    const half2 hinf = __floats2half2_rn(65504.f, 65504.f);
    #pragma unroll
    for (int mt = 0; mt < 2; mt++)
        #pragma unroll
        for (int nt = 0; nt < 8; nt++) {
            bwd2[mt][nt][0] = hinf;
            bwd2[mt][nt][1] = hinf;
        }

    // ---- stage loader (A 8KB + B 16KB per stage) ----
    auto issue_stage = [&](uint32_t aB, uint32_t bB, const __nv_bfloat16* px,
                           const __nv_bfloat16* py) {
        #pragma unroll
        for (int it = 0; it < 4; ++it)
            cp_async16(aB + cwoff + it * rowStride16, px + (size_t)(it * 16) * DD);
        #pragma unroll
        for (int it = 0; it < 8; ++it)
            cp_async16(bB + cwoff + it * rowStride16, py + (size_t)(it * 16) * DD);
        asm volatile("cp.async.commit_group;" ::: "memory");
    };

    // preload stage 0 into buf 0
    issue_stage(aBufs[0], bBufs[0], pxa, pyb);

    // ---- norms -> smem (one-time; ordered by the stage-0 __syncthreads) ----
    #pragma unroll
    for (int i = 0; i < 4; ++i) {
        int idx = tid + i * 128;     // 0..511
        int b = idx >> 6, r = idx & 63;
        s_x2[idx] = g_x2[b * NN + nTile + r];
    }
    #pragma unroll
    for (int i = 0; i < 8; ++i) {
        int idx = tid + i * 128;     // 0..1023
        int b = idx >> 7, cl = idx & 127;
        s_y2[idx] = g_y2[b * MM + mTile + cl];
    }

    for (int b = 0; b < BB; ++b) {
        #pragma unroll
        for (int ch = 0; ch < 2; ++ch) {
            const int s   = b * 2 + ch;
            const uint32_t aBase = aBufs[ch];
            const uint32_t bBase = bBufs[ch];

            // stage s complete; visible to all; other buffer freed
            asm volatile("cp.async.wait_group 0;" ::: "memory");
            __syncthreads();

            // kk=0 fragments FIRST (latency overlaps cp.async burst below)
            uint32_t af[2][2][4], bf[2][4][4];
            ldsm4(af[0][0], aBase + aOff);
            ldsm4(af[0][1], aBase + aOff + (uint32_t)(16 * ST) * 4);
            ldsm4(bf[0][0], bBase + bOff);
            ldsm4(bf[0][1], bBase + bOff + (uint32_t)(16 * ST) * 4);
            ldsm4(bf[0][2], bBase + bOff + (uint32_t)(32 * ST) * 4);
            ldsm4(bf[0][3], bBase + bOff + (uint32_t)(48 * ST) * 4);

            // issue stage s+1 into the other buffer
            const size_t off = (ch == 1) ? ((size_t)NN * DD - BK) : (size_t)BK;
            if (s + 1 < NSTEPS)
                issue_stage(aBufs[ch ^ 1], bBufs[ch ^ 1], pxa + off, pyb + off);
            else
                asm volatile("cp.async.commit_group;" ::: "memory");
            pxa += off;
            pyb += off;

            // ---- compute: 4 k16 sub-steps, fragment double-buffered ----
            #pragma unroll
            for (int kk = 0; kk < 4; ++kk) {
                const int pb = kk & 1;
                if (kk < 3) {
                    const uint32_t ko = (uint32_t)((kk + 1) * 32);
                    ldsm4(af[pb ^ 1][0], aBase + aOff + ko);
                    ldsm4(af[pb ^ 1][1], aBase + aOff + (uint32_t)(16 * ST) * 4 + ko);
                    ldsm4(bf[pb ^ 1][0], bBase + bOff + ko);
                    ldsm4(bf[pb ^ 1][1], bBase + bOff + (uint32_t)(16 * ST) * 4 + ko);
                    ldsm4(bf[pb ^ 1][2], bBase + bOff + (uint32_t)(32 * ST) * 4 + ko);
                    ldsm4(bf[pb ^ 1][3], bBase + bOff + (uint32_t)(48 * ST) * 4 + ko);
                }
                #pragma unroll
                for (int mt = 0; mt < 2; ++mt)
                    #pragma unroll
                    for (int ntp = 0; ntp < 4; ++ntp) {
                        mma_bf16(c[mt][2 * ntp],     af[pb][mt], &bf[pb][ntp][0]);
                        mma_bf16(c[mt][2 * ntp + 1], af[pb][mt], &bf[pb][ntp][2]);
                    }
            }

            if (ch == 1) {
                // ---- epilogue for batch b (norms from smem) ----
                float x2v[2][2], y2v[8][2];
                #pragma unroll
                for (int mt = 0; mt < 2; mt++) {
                    int r = b * 64 + mWarp * 32 + mt * 16 + g;
                    x2v[mt][0] = s_x2[r];
                    x2v[mt][1] = s_x2[r + 8];
                }
                #pragma unroll
                for (int nt = 0; nt < 8; nt++) {
                    int col = b * 128 + nWarp * 64 + nt * 8 + 2 * tig;
                    y2v[nt][0] = s_y2[col];
                    y2v[nt][1] = s_y2[col + 1];
                }

                #pragma unroll
                for (int nt = 0; nt < 8; nt++) {
                    float cm0 = INFINITY, cm1 = INFINITY;
                    #pragma unroll
                    for (int mt = 0; mt < 2; mt++) {
                        #pragma unroll
                        for (int h = 0; h < 2; h++) {
                            float xy0 = c[mt][nt][2 * h + 0];
                            float xy1 = c[mt][nt][2 * h + 1];
                            float d20 = fmaxf(fmaf(-2.f, xy0, x2v[mt][h] + y2v[nt][0]), 0.f);
                            float d21 = fmaxf(fmaf(-2.f, xy1, x2v[mt][h] + y2v[nt][1]), 0.f);
                            bwd2[mt][nt][h] =
                                __hmin2(bwd2[mt][nt][h], __floats2half2_rn(d20, d21));
                            cm0 = fminf(cm0, d20);
                            cm1 = fminf(cm1, d21);
                            c[mt][nt][2 * h + 0] = 0.f;
                            c[mt][nt][2 * h + 1] = 0.f;
                        }
                    }
                    // reduce over the 8 row-groups (lanes differing in g)
                    #pragma unroll
                    for (int o = 4; o <= 16; o <<= 1) {
                        cm0 = fminf(cm0, __shfl_xor_sync(0xffffffffu, cm0, o));
                        cm1 = fminf(cm1, __shfl_xor_sync(0xffffffffu, cm1, o));
                    }
                    if (g == 0) {
                        int col = b * MM + mTile + nWarp * 64 + nt * 8 + 2 * tig;
                        atomicMin(&g_fwd[col],     __float_as_uint(cm0));
                        atomicMin(&g_fwd[col + 1], __float_as_uint(cm1));
                    }
                }
            }
        }
    }

    // ---- backward: min over b complete -> sqrt + block sum ----
    float bsum = 0.f;
    #pragma unroll
    for (int mt = 0; mt < 2; mt++)
        #pragma unroll
        for (int nt = 0; nt < 8; nt++)
            #pragma unroll
            for (int h = 0; h < 2; h++) {
                float2 f = __half22float2(bwd2[mt][nt][h]);
                bsum += sqrtf(f.x) + sqrtf(f.y);
            }
    #pragma unroll
    for (int o = 16; o; o >>= 1) bsum += __shfl_xor_sync(0xffffffffu, bsum, o);
    if (lane == 0) red[wid] = bsum;
    __syncthreads();
    if (tid < 4) {
        float v = red[tid];
        #pragma unroll
        for (int o = 2; o; o >>= 1) v += __shfl_xor_sync(0xfu, v, o);
        if (tid == 0) g_bwd_part[blockIdx.y * gridDim.x + blockIdx.x] = v;
    }
}

// ---------------------------------------------------------------------------
// 128 blocks x 256 threads, 1 element per thread.
__global__ void fwd_reduce_kernel() {
    __shared__ float red[8];
    int tid = threadIdx.x;
    float s = sqrtf(__uint_as_float(g_fwd[blockIdx.x * 256 + tid]));
    #pragma unroll
    for (int o = 16; o; o >>= 1) s += __shfl_xor_sync(0xffffffffu, s, o);
    if ((tid & 31) == 0) red[tid >> 5] = s;
    __syncthreads();
    if (tid < 8) {
        float v = red[tid];
        #pragma unroll
        for (int o = 4; o; o >>= 1) v += __shfl_xor_sync(0xffu, v, o);
        if (tid == 0) g_fwd_part[blockIdx.x] = v;
    }
}

__global__ void final_kernel(float* __restrict__ out) {
    __shared__ float red[256];
    int tid = threadIdx.x;

    float s1 = (tid < 128) ? g_fwd_part[tid] : 0.f;
    float s2 = 0.f;
    #pragma unroll
    for (int r = 0; r < 8; r++)
        s2 += g_bwd_part[r * 256 + tid];

    red[tid] = s1;
    __syncthreads();
    for (int o = 128; o; o >>= 1) {
        if (tid < o) red[tid] += red[tid + o];
        __syncthreads();
    }
    float fwd_sum = red[0];
    __syncthreads();

    red[tid] = s2;
    __syncthreads();
    for (int o = 128; o; o >>= 1) {
        if (tid < o) red[tid] += red[tid + o];
        __syncthreads();
    }

    if (tid == 0)
        out[0] = fwd_sum / (float)(BB * MM) + red[0] / ((float)NN * (float)MM);
}

// ---------------------------------------------------------------------------
extern "C" void kernel_launch(void* const* d_in, const int* in_sizes, int n_in,
                              void* d_out, int out_size) {
    const float* X = (const float*)d_in[0];   // predicted_set (B,N,D)
    const float* Y = (const float*)d_in[1];   // target_set    (B,M,D)

    prepass_kernel<<<(BB * NN + BB * MM) / 16, 256>>>(X, Y);
    dim3 grid(MM / 128, NN / 64);
    chamfer_mma<<<grid, 128>>>();
    fwd_reduce_kernel<<<128, 256>>>();
    final_kernel<<<1, 256>>>((float*)d_out);
}